// round 15
// baseline (speedup 1.0000x reference)
#include <cuda_runtime.h>
#include <cuda_fp16.h>
#include <math.h>
#include <stdint.h>

// Problem constants
#define DIM    1024
#define NEXP   4
#define BATCH  8
#define SEQ    4096
#define NPE    1024
#define MROWS  8192
#define INNER  4096

#define BM 128
#define BN 128
#define BK 64                // halves per k-tile (128 bytes)
#define SKH 72               // halves per smem row (64 + 8 pad) -> 144B stride
#define STAGES 3
#define TILE_HALVES (128 * SKH)                    // 9216
#define SMEM_BYTES  (2 * STAGES * TILE_HALVES * 2) // 110592
#define AOFF_STEP (16 * SKH * 2)                   // 2304 bytes between 16-row groups

// Scratch (device globals; allocation-free)
__device__ __half g_hh[(size_t)BATCH * SEQ * DIM];           // 64 MB
__device__ __half g_w1h[(size_t)INNER * DIM];                // 8 MB
__device__ __half g_w2h[(size_t)DIM * INNER];                // 8 MB
__device__ __half g_inner[(size_t)NEXP * MROWS * INNER];     // 256 MB

// ---------------------------------------------------------------------------
__device__ __forceinline__ uint32_t pack2(float a, float b) {
    __half2 h = __floats2half2_rn(a, b);
    return *reinterpret_cast<uint32_t*>(&h);
}

// fp32-accumulate HMMA (gemm2 path)
__device__ __forceinline__ void mma16(float* c, const uint32_t* a, uint32_t b0, uint32_t b1) {
    asm volatile(
        "mma.sync.aligned.m16n8k16.row.col.f32.f16.f16.f32 "
        "{%0,%1,%2,%3}, {%4,%5,%6,%7}, {%8,%9}, {%0,%1,%2,%3};\n"
        : "+f"(c[0]), "+f"(c[1]), "+f"(c[2]), "+f"(c[3])
        : "r"(a[0]), "r"(a[1]), "r"(a[2]), "r"(a[3]), "r"(b0), "r"(b1));
}

// fp16-accumulate HMMA (gemm1 experiment): C/D are 2x f16x2 regs
__device__ __forceinline__ void mma16h(uint32_t* c, const uint32_t* a, uint32_t b0, uint32_t b1) {
    asm volatile(
        "mma.sync.aligned.m16n8k16.row.col.f16.f16.f16.f16 "
        "{%0,%1}, {%2,%3,%4,%5}, {%6,%7}, {%0,%1};\n"
        : "+r"(c[0]), "+r"(c[1])
        : "r"(a[0]), "r"(a[1]), "r"(a[2]), "r"(a[3]), "r"(b0), "r"(b1));
}

__device__ __forceinline__ void ldsm4(uint32_t* r, uint32_t saddr) {
    asm volatile("ldmatrix.sync.aligned.m8n8.x4.shared.b16 {%0,%1,%2,%3}, [%4];"
                 : "=r"(r[0]), "=r"(r[1]), "=r"(r[2]), "=r"(r[3]) : "r"(saddr));
}

__device__ __forceinline__ void cp16(__half* smem_dst, const __half* gsrc) {
    unsigned s = (unsigned)__cvta_generic_to_shared(smem_dst);
    asm volatile("cp.async.cg.shared.global [%0], [%1], 16;\n" :: "r"(s), "l"(gsrc));
}
#define CP_COMMIT() asm volatile("cp.async.commit_group;\n" ::: "memory")
#define CP_WAIT1()  asm volatile("cp.async.wait_group 1;\n" ::: "memory")

__device__ __forceinline__ float gelu_exact(float v) {
    return 0.5f * v * (1.0f + erff(v * 0.70710678118654752f));
}
__device__ __forceinline__ size_t tok_of(int r, int e) {
    return (size_t)(r >> 10) * SEQ + (size_t)e * NPE + (r & 1023);
}

// ---------------------------------------------------------------------------
__global__ void prep_kernel(const float* __restrict__ w1, const float* __restrict__ w2) {
    size_t i = ((size_t)blockIdx.x * blockDim.x + threadIdx.x) * 4;
    if (i >= (size_t)INNER * DIM) return;
    float4 a = *(const float4*)(w1 + i);
    float4 b = *(const float4*)(w2 + i);
    *(uint2*)(g_w1h + i) = make_uint2(pack2(a.x, a.y), pack2(a.z, a.w));
    *(uint2*)(g_w2h + i) = make_uint2(pack2(b.x, b.y), pack2(b.z, b.w));
}

// ---------------------------------------------------------------------------
// LayerNorm -> half h only
// ---------------------------------------------------------------------------
__global__ void ln_kernel(const float* __restrict__ x,
                          const float* __restrict__ nw,
                          const float* __restrict__ nb) {
    size_t g = blockIdx.x;
    int t = threadIdx.x;
    const float4* xp = reinterpret_cast<const float4*>(x + g * DIM);
    float4 v = xp[t];
    float s  = v.x + v.y + v.z + v.w;
    float sq = v.x * v.x + v.y * v.y + v.z * v.z + v.w * v.w;
    #pragma unroll
    for (int o = 16; o; o >>= 1) {
        s  += __shfl_xor_sync(0xffffffffu, s,  o);
        sq += __shfl_xor_sync(0xffffffffu, sq, o);
    }
    __shared__ float ss[8], ssq[8];
    __shared__ float mu_s, rs_s;
    int wid = t >> 5, lid = t & 31;
    if (lid == 0) { ss[wid] = s; ssq[wid] = sq; }
    __syncthreads();
    if (t == 0) {
        float S = 0.f, SQ = 0.f;
        #pragma unroll
        for (int i = 0; i < 8; i++) { S += ss[i]; SQ += ssq[i]; }
        float mu = S * (1.0f / DIM);
        float var = SQ * (1.0f / DIM) - mu * mu;
        mu_s = mu; rs_s = rsqrtf(var + 1e-5f);
    }
    __syncthreads();
    float mu = mu_s, rs = rs_s;
    float4 wv = reinterpret_cast<const float4*>(nw)[t];
    float4 bv = reinterpret_cast<const float4*>(nb)[t];
    float h0 = (v.x - mu) * rs * wv.x + bv.x;
    float h1 = (v.y - mu) * rs * wv.y + bv.y;
    float h2 = (v.z - mu) * rs * wv.z + bv.z;
    float h3 = (v.w - mu) * rs * wv.w + bv.w;
    *(uint2*)(g_hh + g * DIM + t * 4) = make_uint2(pack2(h0, h1), pack2(h2, h3));
}

// ---------------------------------------------------------------------------
// fragment groups
// ---------------------------------------------------------------------------
__device__ __forceinline__ void ld_group(uint32_t af[4][4], uint32_t bf[8],
                                         unsigned aBase, unsigned bBase, unsigned kb) {
    #pragma unroll
    for (int mi = 0; mi < 4; ++mi)
        ldsm4(af[mi], aBase + mi * AOFF_STEP + kb);
    ldsm4(bf,     bBase + kb);
    ldsm4(bf + 4, bBase + AOFF_STEP + kb);
}

// fp32-acc group (gemm2)
__device__ __forceinline__ void mma_group(float acc[4][4][4],
                                          uint32_t af[4][4], uint32_t bf[8]) {
    #pragma unroll
    for (int mi = 0; mi < 4; ++mi) {
        mma16(acc[mi][0], af[mi], bf[0], bf[2]);
        mma16(acc[mi][1], af[mi], bf[1], bf[3]);
        mma16(acc[mi][2], af[mi], bf[4], bf[6]);
        mma16(acc[mi][3], af[mi], bf[5], bf[7]);
    }
}

__device__ __forceinline__ void compute_tile(float acc[4][4][4],
                                             unsigned aBase, unsigned bBase) {
    uint32_t af[2][4][4], bf[2][8];
    ld_group(af[0], bf[0], aBase, bBase, 0);
    #pragma unroll
    for (int ks = 0; ks < 4; ++ks) {
        const int cur = ks & 1, nxt = cur ^ 1;
        if (ks < 3)
            ld_group(af[nxt], bf[nxt], aBase, bBase, (unsigned)((ks + 1) * 32));
        mma_group(acc, af[cur], bf[cur]);
    }
}

// fp16-acc group (gemm1): transient fp16 C per MMA, promoted immediately
__device__ __forceinline__ void mma_group_h(float acc[4][4][4],
                                            uint32_t af[4][4], uint32_t bf[8]) {
    #pragma unroll
    for (int mi = 0; mi < 4; ++mi) {
        #pragma unroll
        for (int nj = 0; nj < 4; ++nj) {
            const uint32_t b0 = (nj == 0) ? bf[0] : (nj == 1) ? bf[1] : (nj == 2) ? bf[4] : bf[5];
            const uint32_t b1 = (nj == 0) ? bf[2] : (nj == 1) ? bf[3] : (nj == 2) ? bf[6] : bf[7];
            uint32_t c[2] = {0u, 0u};
            mma16h(c, af[mi], b0, b1);
            float2 f01 = __half22float2(*reinterpret_cast<__half2*>(&c[0]));
            float2 f23 = __half22float2(*reinterpret_cast<__half2*>(&c[1]));
            acc[mi][nj][0] += f01.x;
            acc[mi][nj][1] += f01.y;
            acc[mi][nj][2] += f23.x;
            acc[mi][nj][3] += f23.y;
        }
    }
}

__device__ __forceinline__ void compute_tile_h(float acc[4][4][4],
                                               unsigned aBase, unsigned bBase) {
    #pragma unroll
    for (int ks = 0; ks < 4; ++ks) {
        uint32_t af[4][4], bf[8];
        ld_group(af, bf, aBase, bBase, (unsigned)(ks * 32));
        mma_group_h(acc, af, bf);
    }
}

// ---------------------------------------------------------------------------
// GEMM1: inner[e] = gelu( h[:, :K] @ w1[:, :K]^T + b1 )   grid (32, 64, 4), 256 thr
// fp16-accumulate HMMA experiment
// ---------------------------------------------------------------------------
__global__ __launch_bounds__(256, 2)
void gemm1_fp16(const float* __restrict__ l1b) {
    extern __shared__ __half smem[];
    __half* As = smem;
    __half* Bs = smem + STAGES * TILE_HALVES;

    const int e  = blockIdx.z;
    const int KT = 16 >> e;
    const int tid  = threadIdx.x;
    const int srow = tid >> 3;
    const int chk  = tid & 7;

    const __half* aA0 = g_hh + tok_of(blockIdx.y * BM + srow, e) * DIM + chk * 8;
    const __half* aB0 = g_w1h + (size_t)(blockIdx.x * BN + srow) * DIM + chk * 8;
    const int so0 = srow * SKH + chk * 8;

    #pragma unroll
    for (int s = 0; s < STAGES - 1; ++s) {
        if (s < KT) {
            __half* a = As + s * TILE_HALVES;
            __half* b = Bs + s * TILE_HALVES;
            size_t off = (size_t)s * BK;
            #pragma unroll
            for (int i = 0; i < 4; ++i) {
                cp16(a + so0 + i * 32 * SKH, aA0 + off + (size_t)(32 * i) * DIM);
                cp16(b + so0 + i * 32 * SKH, aB0 + off + (size_t)(32 * i) * DIM);
            }
        }
        CP_COMMIT();
    }

    const int wid = tid >> 5, lane = tid & 31;
    const int mBase = (wid & 1) * 64;
    const int nBase = (wid >> 1) * 32;
    const int lrow = lane & 15, lhalf = lane >> 4;

    const unsigned aS0 = (unsigned)__cvta_generic_to_shared(As)
                       + (unsigned)((mBase + lrow) * (SKH * 2) + lhalf * 16);
    const unsigned bS0 = (unsigned)__cvta_generic_to_shared(Bs)
                       + (unsigned)((nBase + lrow) * (SKH * 2) + lhalf * 16);

    float acc[4][4][4];
    #pragma unroll
    for (int i = 0; i < 4; i++)
        #pragma unroll
        for (int j = 0; j < 4; j++)
            #pragma unroll
            for (int k = 0; k < 4; k++) acc[i][j][k] = 0.f;

    for (int kt = 0; kt < KT; ++kt) {
        CP_WAIT1();
        __syncthreads();
        const int pf = kt + STAGES - 1;
        if (pf < KT) {
            int sb = pf; while (sb >= STAGES) sb -= STAGES;
            __half* a = As + sb * TILE_HALVES;
            __half* b = Bs + sb * TILE_HALVES;
            size_t off = (size_t)pf * BK;
            #pragma unroll
            for (int i = 0; i < 4; ++i) {
                cp16(a + so0 + i * 32 * SKH, aA0 + off + (size_t)(32 * i) * DIM);
                cp16(b + so0 + i * 32 * SKH, aB0 + off + (size_t)(32 * i) * DIM);
            }
        }
        CP_COMMIT();
        int st = kt; while (st >= STAGES) st -= STAGES;
        const unsigned sbyte = (unsigned)(st * TILE_HALVES * 2);
        compute_tile_h(acc, aS0 + sbyte, bS0 + sbyte);
    }

    __half* innE = g_inner + (size_t)e * MROWS * INNER;
    const int lm = lane >> 2, lk = lane & 3;
    const int rT = blockIdx.y * BM + mBase;
    const int cT = blockIdx.x * BN + nBase;
    #pragma unroll
    for (int mi = 0; mi < 4; mi++) {
        int r0 = rT + mi * 16 + lm;
        #pragma unroll
        for (int ni = 0; ni < 4; ni++) {
            int c0 = cT + ni * 8 + lk * 2;
            float bv0 = __ldg(l1b + c0), bv1 = __ldg(l1b + c0 + 1);
            uint32_t lo = pack2(gelu_exact(acc[mi][ni][0] + bv0),
                                gelu_exact(acc[mi][ni][1] + bv1));
            uint32_t hi = pack2(gelu_exact(acc[mi][ni][2] + bv0),
                                gelu_exact(acc[mi][ni][3] + bv1));
            *(uint32_t*)&innE[(size_t)r0 * INNER + c0]       = lo;
            *(uint32_t*)&innE[(size_t)(r0 + 8) * INNER + c0] = hi;
        }
    }
}

// ---------------------------------------------------------------------------
// GEMM2: out[:, :m] = x + scale*( inner[e] @ w2[:m,:]^T + b2[:m] )
//        out[:, m:] = x   (passthrough slots, overlap the GEMM waves)
// grid (32, 64): slot -> e = slot>>3, nx = slot&7; 256 thr.  fp32 accumulate.
// ---------------------------------------------------------------------------
__global__ __launch_bounds__(256, 2)
void gemm2_fp16(const float* __restrict__ x,
                const float* __restrict__ rp,
                const float* __restrict__ alpha_p,
                const float* __restrict__ l2b,
                float* __restrict__ out) {
    const int slot = blockIdx.x;
    const int e  = slot >> 3;
    const int nx = slot & 7;
    const int m  = DIM >> e;
    const int tid = threadIdx.x;

    if (nx * BN >= m) {
        const int r0 = tid >> 5;
        const int c4 = tid & 31;
        #pragma unroll
        for (int it = 0; it < 16; ++it) {
            int rloc = blockIdx.y * BM + r0 + it * 8;
            size_t g = tok_of(rloc, e);
            const float4* src = (const float4*)(x + g * DIM + nx * BN) + c4;
            float4* dst = (float4*)(out + g * DIM + nx * BN) + c4;
            *dst = *src;
        }
        return;
    }

    extern __shared__ __half smem[];
    __half* As = smem;
    __half* Bs = smem + STAGES * TILE_HALVES;

    const int KT = INNER / BK;     // 64
    const int srow = tid >> 3;
    const int chk  = tid & 7;

    const __half* innE = g_inner + (size_t)e * MROWS * INNER;
    const __half* aA0 = innE + (size_t)(blockIdx.y * BM + srow) * INNER + chk * 8;
    const __half* aB0 = g_w2h + (size_t)(nx * BN + srow) * INNER + chk * 8;
    const int so0 = srow * SKH + chk * 8;

    #pragma unroll
    for (int s = 0; s < STAGES - 1; ++s) {
        __half* a = As + s * TILE_HALVES;
        __half* b = Bs + s * TILE_HALVES;
        size_t off = (size_t)s * BK;
        #pragma unroll
        for (int i = 0; i < 4; ++i) {
            cp16(a + so0 + i * 32 * SKH, aA0 + off + (size_t)(32 * i) * INNER);
            cp16(b + so0 + i * 32 * SKH, aB0 + off + (size_t)(32 * i) * INNER);
        }
        CP_COMMIT();
    }

    const int wid = tid >> 5, lane = tid & 31;
    const int mBase = (wid & 1) * 64;
    const int nBase = (wid >> 1) * 32;
    const int lrow = lane & 15, lhalf = lane >> 4;

    const unsigned aS0 = (unsigned)__cvta_generic_to_shared(As)
                       + (unsigned)((mBase + lrow) * (SKH * 2) + lhalf * 16);
    const unsigned bS0 = (unsigned)__cvta_generic_to_shared(Bs)
                       + (unsigned)((nBase + lrow) * (SKH * 2) + lhalf * 16);

    float acc[4][4][4];
    #pragma unroll
    for (int i = 0; i < 4; i++)
        #pragma unroll
        for (int j = 0; j < 4; j++)
            #pragma unroll
            for (int k = 0; k < 4; k++) acc[i][j][k] = 0.f;

    for (int kt = 0; kt < KT; ++kt) {
        CP_WAIT1();
        __syncthreads();
        const int pf = kt + STAGES - 1;
        if (pf < KT) {
            int sb = pf; while (sb >= STAGES) sb -= STAGES;
            __half* a = As + sb * TILE_HALVES;
            __half* b = Bs + sb * TILE_HALVES;
            size_t off = (size_t)pf * BK;
            #pragma unroll
            for (int i = 0; i < 4; ++i) {
                cp16(a + so0 + i * 32 * SKH, aA0 + off + (size_t)(32 * i) * INNER);
                cp16(b + so0 + i * 32 * SKH, aB0 + off + (size_t)(32 * i) * INNER);
            }
        }
        CP_COMMIT();
        int st = kt; while (st >= STAGES) st -= STAGES;
        const unsigned sbyte = (unsigned)(st * TILE_HALVES * 2);
        compute_tile(acc, aS0 + sbyte, bS0 + sbyte);
    }

    const float al = __ldg(alpha_p);
    const int lm = lane >> 2, lk = lane & 3;
    const int rT = blockIdx.y * BM + mBase;
    const int cT = nx * BN + nBase;
    #pragma unroll
    for (int mi = 0; mi < 4; mi++) {
        int rloc = rT + mi * 16 + lm;
        size_t g0 = tok_of(rloc, e);
        size_t g1 = tok_of(rloc + 8, e);
        float sc0 = al * __ldg(rp + g0 * NEXP + e) + 1.0f;
        float sc1 = al * __ldg(rp + g1 * NEXP + e) + 1.0f;
        #pragma unroll
        for (int ni = 0; ni < 4; ni++) {
            int c0 = cT + ni * 8 + lk * 2;
            float bv0 = __ldg(l2b + c0), bv1 = __ldg(l2b + c0 + 1);
            float2 xv0 = *(const float2*)&x[g0 * DIM + c0];
            float2 xv1 = *(const float2*)&x[g1 * DIM + c0];
            float2 o0 = make_float2(xv0.x + sc0 * (acc[mi][ni][0] + bv0),
                                    xv0.y + sc0 * (acc[mi][ni][1] + bv1));
            float2 o1 = make_float2(xv1.x + sc1 * (acc[mi][ni][2] + bv0),
                                    xv1.y + sc1 * (acc[mi][ni][3] + bv1));
            *(float2*)&out[g0 * DIM + c0] = o0;
            *(float2*)&out[g1 * DIM + c0] = o1;
        }
    }
}

// ---------------------------------------------------------------------------
extern "C" void kernel_launch(void* const* d_in, const int* in_sizes, int n_in,
                              void* d_out, int out_size) {
    const float* x     = (const float*)d_in[0];
    const float* rp    = (const float*)d_in[1];
    const float* alpha = (const float*)d_in[2];
    const float* nw    = (const float*)d_in[3];
    const float* nb    = (const float*)d_in[4];
    const float* l1w   = (const float*)d_in[5];
    const float* l1b   = (const float*)d_in[6];
    const float* l2w   = (const float*)d_in[7];
    const float* l2b   = (const float*)d_in[8];
    float* out = (float*)d_out;

    static bool attr_done = false;
    if (!attr_done) {
        cudaFuncSetAttribute(gemm1_fp16, cudaFuncAttributeMaxDynamicSharedMemorySize, SMEM_BYTES);
        cudaFuncSetAttribute(gemm2_fp16, cudaFuncAttributeMaxDynamicSharedMemorySize, SMEM_BYTES);
        attr_done = true;
    }

    prep_kernel<<<(INNER * DIM / 4 + 255) / 256, 256>>>(l1w, l2w);
    ln_kernel<<<BATCH * SEQ, 256>>>(x, nw, nb);

    dim3 g1(INNER / BN, MROWS / BM, NEXP);   // (32, 64, 4)
    gemm1_fp16<<<g1, 256, SMEM_BYTES>>>(l1b);

    dim3 g2(32, MROWS / BM);                 // all (e, n)-slots incl. passthrough
    gemm2_fp16<<<g2, 256, SMEM_BYTES>>>(x, rp, alpha, l2b, out);
}

// round 16
// speedup vs baseline: 1.2407x; 1.2407x over previous
#include <cuda_runtime.h>
#include <cuda_fp16.h>
#include <math.h>
#include <stdint.h>

// Problem constants
#define DIM    1024
#define NEXP   4
#define BATCH  8
#define SEQ    4096
#define NPE    1024
#define MROWS  8192
#define INNER  4096

#define BM 128
#define BN 128
#define BK 64                // halves per k-tile (128 bytes)
#define SKH 72               // halves per smem row (64 + 8 pad) -> 144B stride
#define STAGES 3
#define TILE_HALVES (128 * SKH)                    // 9216
#define SMEM_BYTES  (2 * STAGES * TILE_HALVES * 2) // 110592
#define AOFF_STEP (16 * SKH * 2)                   // 2304 bytes between 16-row groups

// Scratch (device globals; allocation-free)
__device__ __half g_hh[(size_t)BATCH * SEQ * DIM];           // 64 MB
__device__ __half g_w1h[(size_t)INNER * DIM];                // 8 MB
__device__ __half g_w2h[(size_t)DIM * INNER];                // 8 MB
__device__ __half g_inner[(size_t)NEXP * MROWS * INNER];     // 256 MB

// ---------------------------------------------------------------------------
__device__ __forceinline__ uint32_t pack2(float a, float b) {
    __half2 h = __floats2half2_rn(a, b);
    return *reinterpret_cast<uint32_t*>(&h);
}

__device__ __forceinline__ void mma16(float* c, const uint32_t* a, uint32_t b0, uint32_t b1) {
    asm volatile(
        "mma.sync.aligned.m16n8k16.row.col.f32.f16.f16.f32 "
        "{%0,%1,%2,%3}, {%4,%5,%6,%7}, {%8,%9}, {%0,%1,%2,%3};\n"
        : "+f"(c[0]), "+f"(c[1]), "+f"(c[2]), "+f"(c[3])
        : "r"(a[0]), "r"(a[1]), "r"(a[2]), "r"(a[3]), "r"(b0), "r"(b1));
}

__device__ __forceinline__ void ldsm4(uint32_t* r, uint32_t saddr) {
    asm volatile("ldmatrix.sync.aligned.m8n8.x4.shared.b16 {%0,%1,%2,%3}, [%4];"
                 : "=r"(r[0]), "=r"(r[1]), "=r"(r[2]), "=r"(r[3]) : "r"(saddr));
}

__device__ __forceinline__ void cp16(__half* smem_dst, const __half* gsrc) {
    unsigned s = (unsigned)__cvta_generic_to_shared(smem_dst);
    asm volatile("cp.async.cg.shared.global [%0], [%1], 16;\n" :: "r"(s), "l"(gsrc));
}
#define CP_COMMIT() asm volatile("cp.async.commit_group;\n" ::: "memory")
#define CP_WAIT1()  asm volatile("cp.async.wait_group 1;\n" ::: "memory")

__device__ __forceinline__ float gelu_exact(float v) {
    return 0.5f * v * (1.0f + erff(v * 0.70710678118654752f));
}
__device__ __forceinline__ size_t tok_of(int r, int e) {
    return (size_t)(r >> 10) * SEQ + (size_t)e * NPE + (r & 1023);
}

// ---------------------------------------------------------------------------
__global__ void prep_kernel(const float* __restrict__ w1, const float* __restrict__ w2) {
    size_t i = ((size_t)blockIdx.x * blockDim.x + threadIdx.x) * 4;
    if (i >= (size_t)INNER * DIM) return;
    float4 a = *(const float4*)(w1 + i);
    float4 b = *(const float4*)(w2 + i);
    *(uint2*)(g_w1h + i) = make_uint2(pack2(a.x, a.y), pack2(a.z, a.w));
    *(uint2*)(g_w2h + i) = make_uint2(pack2(b.x, b.y), pack2(b.z, b.w));
}

// ---------------------------------------------------------------------------
// LayerNorm -> half h only (residual passthrough handled by gemm2 copy slots)
// ---------------------------------------------------------------------------
__global__ void ln_kernel(const float* __restrict__ x,
                          const float* __restrict__ nw,
                          const float* __restrict__ nb) {
    size_t g = blockIdx.x;
    int t = threadIdx.x;
    const float4* xp = reinterpret_cast<const float4*>(x + g * DIM);
    float4 v = xp[t];
    float s  = v.x + v.y + v.z + v.w;
    float sq = v.x * v.x + v.y * v.y + v.z * v.z + v.w * v.w;
    #pragma unroll
    for (int o = 16; o; o >>= 1) {
        s  += __shfl_xor_sync(0xffffffffu, s,  o);
        sq += __shfl_xor_sync(0xffffffffu, sq, o);
    }
    __shared__ float ss[8], ssq[8];
    __shared__ float mu_s, rs_s;
    int wid = t >> 5, lid = t & 31;
    if (lid == 0) { ss[wid] = s; ssq[wid] = sq; }
    __syncthreads();
    if (t == 0) {
        float S = 0.f, SQ = 0.f;
        #pragma unroll
        for (int i = 0; i < 8; i++) { S += ss[i]; SQ += ssq[i]; }
        float mu = S * (1.0f / DIM);
        float var = SQ * (1.0f / DIM) - mu * mu;
        mu_s = mu; rs_s = rsqrtf(var + 1e-5f);
    }
    __syncthreads();
    float mu = mu_s, rs = rs_s;
    float4 wv = reinterpret_cast<const float4*>(nw)[t];
    float4 bv = reinterpret_cast<const float4*>(nb)[t];
    float h0 = (v.x - mu) * rs * wv.x + bv.x;
    float h1 = (v.y - mu) * rs * wv.y + bv.y;
    float h2 = (v.z - mu) * rs * wv.z + bv.z;
    float h3 = (v.w - mu) * rs * wv.w + bv.w;
    *(uint2*)(g_hh + g * DIM + t * 4) = make_uint2(pack2(h0, h1), pack2(h2, h3));
}

// ---------------------------------------------------------------------------
// compute core: warp tile 64x32, one 64-half k-tile, fragment double-buffered
// ---------------------------------------------------------------------------
__device__ __forceinline__ void ld_group(uint32_t af[4][4], uint32_t bf[8],
                                         unsigned aBase, unsigned bBase, unsigned kb) {
    #pragma unroll
    for (int mi = 0; mi < 4; ++mi)
        ldsm4(af[mi], aBase + mi * AOFF_STEP + kb);
    ldsm4(bf,     bBase + kb);
    ldsm4(bf + 4, bBase + AOFF_STEP + kb);
}

__device__ __forceinline__ void mma_group(float acc[4][4][4],
                                          uint32_t af[4][4], uint32_t bf[8]) {
    #pragma unroll
    for (int mi = 0; mi < 4; ++mi) {
        mma16(acc[mi][0], af[mi], bf[0], bf[2]);
        mma16(acc[mi][1], af[mi], bf[1], bf[3]);
        mma16(acc[mi][2], af[mi], bf[4], bf[6]);
        mma16(acc[mi][3], af[mi], bf[5], bf[7]);
    }
}

__device__ __forceinline__ void compute_tile(float acc[4][4][4],
                                             unsigned aBase, unsigned bBase) {
    uint32_t af[2][4][4], bf[2][8];
    ld_group(af[0], bf[0], aBase, bBase, 0);
    #pragma unroll
    for (int ks = 0; ks < 4; ++ks) {
        const int cur = ks & 1, nxt = cur ^ 1;
        if (ks < 3)
            ld_group(af[nxt], bf[nxt], aBase, bBase, (unsigned)((ks + 1) * 32));
        mma_group(acc, af[cur], bf[cur]);
    }
}

// ---------------------------------------------------------------------------
// GEMM1: inner[e] = gelu( h[:, :K] @ w1[:, :K]^T + b1 )   grid (32, 64, 4), 256 thr
// ---------------------------------------------------------------------------
__global__ __launch_bounds__(256, 2)
void gemm1_fp16(const float* __restrict__ l1b) {
    extern __shared__ __half smem[];
    __half* As = smem;
    __half* Bs = smem + STAGES * TILE_HALVES;

    const int e  = blockIdx.z;
    const int KT = 16 >> e;
    const int tid  = threadIdx.x;
    const int srow = tid >> 3;                     // 0..31
    const int chk  = tid & 7;

    const __half* aA0 = g_hh + tok_of(blockIdx.y * BM + srow, e) * DIM + chk * 8;
    const __half* aB0 = g_w1h + (size_t)(blockIdx.x * BN + srow) * DIM + chk * 8;
    const int so0 = srow * SKH + chk * 8;

    #pragma unroll
    for (int s = 0; s < STAGES - 1; ++s) {
        if (s < KT) {
            __half* a = As + s * TILE_HALVES;
            __half* b = Bs + s * TILE_HALVES;
            size_t off = (size_t)s * BK;
            #pragma unroll
            for (int i = 0; i < 4; ++i) {
                cp16(a + so0 + i * 32 * SKH, aA0 + off + (size_t)(32 * i) * DIM);
                cp16(b + so0 + i * 32 * SKH, aB0 + off + (size_t)(32 * i) * DIM);
            }
        }
        CP_COMMIT();
    }

    const int wid = tid >> 5, lane = tid & 31;
    const int mBase = (wid & 1) * 64;
    const int nBase = (wid >> 1) * 32;
    const int lrow = lane & 15, lhalf = lane >> 4;

    const unsigned aS0 = (unsigned)__cvta_generic_to_shared(As)
                       + (unsigned)((mBase + lrow) * (SKH * 2) + lhalf * 16);
    const unsigned bS0 = (unsigned)__cvta_generic_to_shared(Bs)
                       + (unsigned)((nBase + lrow) * (SKH * 2) + lhalf * 16);

    float acc[4][4][4];
    #pragma unroll
    for (int i = 0; i < 4; i++)
        #pragma unroll
        for (int j = 0; j < 4; j++)
            #pragma unroll
            for (int k = 0; k < 4; k++) acc[i][j][k] = 0.f;

    for (int kt = 0; kt < KT; ++kt) {
        CP_WAIT1();
        __syncthreads();
        const int pf = kt + STAGES - 1;
        if (pf < KT) {
            int sb = pf; while (sb >= STAGES) sb -= STAGES;
            __half* a = As + sb * TILE_HALVES;
            __half* b = Bs + sb * TILE_HALVES;
            size_t off = (size_t)pf * BK;
            #pragma unroll
            for (int i = 0; i < 4; ++i) {
                cp16(a + so0 + i * 32 * SKH, aA0 + off + (size_t)(32 * i) * DIM);
                cp16(b + so0 + i * 32 * SKH, aB0 + off + (size_t)(32 * i) * DIM);
            }
        }
        CP_COMMIT();
        int st = kt; while (st >= STAGES) st -= STAGES;
        const unsigned sbyte = (unsigned)(st * TILE_HALVES * 2);
        compute_tile(acc, aS0 + sbyte, bS0 + sbyte);
    }

    __half* innE = g_inner + (size_t)e * MROWS * INNER;
    const int lm = lane >> 2, lk = lane & 3;
    const int rT = blockIdx.y * BM + mBase;
    const int cT = blockIdx.x * BN + nBase;
    #pragma unroll
    for (int mi = 0; mi < 4; mi++) {
        int r0 = rT + mi * 16 + lm;
        #pragma unroll
        for (int ni = 0; ni < 4; ni++) {
            int c0 = cT + ni * 8 + lk * 2;
            float bv0 = __ldg(l1b + c0), bv1 = __ldg(l1b + c0 + 1);
            uint32_t lo = pack2(gelu_exact(acc[mi][ni][0] + bv0),
                                gelu_exact(acc[mi][ni][1] + bv1));
            uint32_t hi = pack2(gelu_exact(acc[mi][ni][2] + bv0),
                                gelu_exact(acc[mi][ni][3] + bv1));
            *(uint32_t*)&innE[(size_t)r0 * INNER + c0]       = lo;
            *(uint32_t*)&innE[(size_t)(r0 + 8) * INNER + c0] = hi;
        }
    }
}

// ---------------------------------------------------------------------------
// GEMM2: out[:, :m] = x + scale*( inner[e] @ w2[:m,:]^T + b2[:m] )
//        out[:, m:] = x   (passthrough slots, overlap the GEMM waves)
// grid (32, 64): slot -> e = slot>>3, nx = slot&7; 256 thr
// ---------------------------------------------------------------------------
__global__ __launch_bounds__(256, 2)
void gemm2_fp16(const float* __restrict__ x,
                const float* __restrict__ rp,
                const float* __restrict__ alpha_p,
                const float* __restrict__ l2b,
                float* __restrict__ out) {
    const int slot = blockIdx.x;
    const int e  = slot >> 3;
    const int nx = slot & 7;
    const int m  = DIM >> e;
    const int tid = threadIdx.x;

    if (nx * BN >= m) {
        // passthrough: out = x for this 128x128 block
        const int r0 = tid >> 5;
        const int c4 = tid & 31;
        #pragma unroll
        for (int it = 0; it < 16; ++it) {
            int rloc = blockIdx.y * BM + r0 + it * 8;
            size_t g = tok_of(rloc, e);
            const float4* src = (const float4*)(x + g * DIM + nx * BN) + c4;
            float4* dst = (float4*)(out + g * DIM + nx * BN) + c4;
            *dst = *src;
        }
        return;
    }

    extern __shared__ __half smem[];
    __half* As = smem;
    __half* Bs = smem + STAGES * TILE_HALVES;

    const int KT = INNER / BK;     // 64
    const int srow = tid >> 3;
    const int chk  = tid & 7;

    const __half* innE = g_inner + (size_t)e * MROWS * INNER;
    const __half* aA0 = innE + (size_t)(blockIdx.y * BM + srow) * INNER + chk * 8;
    const __half* aB0 = g_w2h + (size_t)(nx * BN + srow) * INNER + chk * 8;
    const int so0 = srow * SKH + chk * 8;

    #pragma unroll
    for (int s = 0; s < STAGES - 1; ++s) {
        __half* a = As + s * TILE_HALVES;
        __half* b = Bs + s * TILE_HALVES;
        size_t off = (size_t)s * BK;
        #pragma unroll
        for (int i = 0; i < 4; ++i) {
            cp16(a + so0 + i * 32 * SKH, aA0 + off + (size_t)(32 * i) * INNER);
            cp16(b + so0 + i * 32 * SKH, aB0 + off + (size_t)(32 * i) * INNER);
        }
        CP_COMMIT();
    }

    const int wid = tid >> 5, lane = tid & 31;
    const int mBase = (wid & 1) * 64;
    const int nBase = (wid >> 1) * 32;
    const int lrow = lane & 15, lhalf = lane >> 4;

    const unsigned aS0 = (unsigned)__cvta_generic_to_shared(As)
                       + (unsigned)((mBase + lrow) * (SKH * 2) + lhalf * 16);
    const unsigned bS0 = (unsigned)__cvta_generic_to_shared(Bs)
                       + (unsigned)((nBase + lrow) * (SKH * 2) + lhalf * 16);

    float acc[4][4][4];
    #pragma unroll
    for (int i = 0; i < 4; i++)
        #pragma unroll
        for (int j = 0; j < 4; j++)
            #pragma unroll
            for (int k = 0; k < 4; k++) acc[i][j][k] = 0.f;

    for (int kt = 0; kt < KT; ++kt) {
        CP_WAIT1();
        __syncthreads();
        const int pf = kt + STAGES - 1;
        if (pf < KT) {
            int sb = pf; while (sb >= STAGES) sb -= STAGES;
            __half* a = As + sb * TILE_HALVES;
            __half* b = Bs + sb * TILE_HALVES;
            size_t off = (size_t)pf * BK;
            #pragma unroll
            for (int i = 0; i < 4; ++i) {
                cp16(a + so0 + i * 32 * SKH, aA0 + off + (size_t)(32 * i) * INNER);
                cp16(b + so0 + i * 32 * SKH, aB0 + off + (size_t)(32 * i) * INNER);
            }
        }
        CP_COMMIT();
        int st = kt; while (st >= STAGES) st -= STAGES;
        const unsigned sbyte = (unsigned)(st * TILE_HALVES * 2);
        compute_tile(acc, aS0 + sbyte, bS0 + sbyte);
    }

    const float al = __ldg(alpha_p);
    const int lm = lane >> 2, lk = lane & 3;
    const int rT = blockIdx.y * BM + mBase;
    const int cT = nx * BN + nBase;
    #pragma unroll
    for (int mi = 0; mi < 4; mi++) {
        int rloc = rT + mi * 16 + lm;
        size_t g0 = tok_of(rloc, e);
        size_t g1 = tok_of(rloc + 8, e);
        float sc0 = al * __ldg(rp + g0 * NEXP + e) + 1.0f;
        float sc1 = al * __ldg(rp + g1 * NEXP + e) + 1.0f;
        #pragma unroll
        for (int ni = 0; ni < 4; ni++) {
            int c0 = cT + ni * 8 + lk * 2;
            float bv0 = __ldg(l2b + c0), bv1 = __ldg(l2b + c0 + 1);
            float2 xv0 = *(const float2*)&x[g0 * DIM + c0];
            float2 xv1 = *(const float2*)&x[g1 * DIM + c0];
            float2 o0 = make_float2(xv0.x + sc0 * (acc[mi][ni][0] + bv0),
                                    xv0.y + sc0 * (acc[mi][ni][1] + bv1));
            float2 o1 = make_float2(xv1.x + sc1 * (acc[mi][ni][2] + bv0),
                                    xv1.y + sc1 * (acc[mi][ni][3] + bv1));
            *(float2*)&out[g0 * DIM + c0] = o0;
            *(float2*)&out[g1 * DIM + c0] = o1;
        }
    }
}

// ---------------------------------------------------------------------------
extern "C" void kernel_launch(void* const* d_in, const int* in_sizes, int n_in,
                              void* d_out, int out_size) {
    const float* x     = (const float*)d_in[0];
    const float* rp    = (const float*)d_in[1];
    const float* alpha = (const float*)d_in[2];
    const float* nw    = (const float*)d_in[3];
    const float* nb    = (const float*)d_in[4];
    const float* l1w   = (const float*)d_in[5];
    const float* l1b   = (const float*)d_in[6];
    const float* l2w   = (const float*)d_in[7];
    const float* l2b   = (const float*)d_in[8];
    float* out = (float*)d_out;

    static bool attr_done = false;
    if (!attr_done) {
        cudaFuncSetAttribute(gemm1_fp16, cudaFuncAttributeMaxDynamicSharedMemorySize, SMEM_BYTES);
        cudaFuncSetAttribute(gemm2_fp16, cudaFuncAttributeMaxDynamicSharedMemorySize, SMEM_BYTES);
        attr_done = true;
    }

    prep_kernel<<<(INNER * DIM / 4 + 255) / 256, 256>>>(l1w, l2w);
    ln_kernel<<<BATCH * SEQ, 256>>>(x, nw, nb);

    dim3 g1(INNER / BN, MROWS / BM, NEXP);   // (32, 64, 4)
    gemm1_fp16<<<g1, 256, SMEM_BYTES>>>(l1b);

    dim3 g2(32, MROWS / BM);                 // all (e, n)-slots incl. passthrough
    gemm2_fp16<<<g2, 256, SMEM_BYTES>>>(x, rp, alpha, l2b, out);
}